// round 6
// baseline (speedup 1.0000x reference)
#include <cuda_runtime.h>
#include <cstdint>

// Problem constants
#define MDW   4
#define UDIM  9          // 2*MD+1
#define NB    2
#define NC    128
#define NH    64
#define NW    64
#define NF    16
#define NHW   4096
#define OUT1_ELEMS (NB*NF*4*NHW)        // 524288
#define WARP_ELEMS (NB*NC*NHW)          // 1048576

// cvol scratch: [b*F][uv=du*9+dv][h][w]  (42.5 MB)
__device__ float g_cvol[NB*NF*81*NHW];

typedef unsigned long long u64;

__device__ __forceinline__ u64 pk2(float x, float y) {
    u64 r; asm("mov.b64 %0, {%1,%2};" : "=l"(r) : "f"(x), "f"(y)); return r;
}
__device__ __forceinline__ float2 upk(u64 v) {
    float2 f; asm("mov.b64 {%0,%1}, %2;" : "=f"(f.x), "=f"(f.y) : "l"(v)); return f;
}
__device__ __forceinline__ u64 ffma2(u64 a, u64 b, u64 c) {
    u64 d; asm("fma.rn.f32x2 %0, %1, %2, %3;" : "=l"(d) : "l"(a), "l"(b), "l"(c)); return d;
}

// ---------------------------------------------------------------------------
// Kernel A: cost volume + channel projection.
// grid (dv=9, h=64, b=2), block 288 (9 warps, warp <-> du), 2 blocks/SM.
// lane <-> pixels (l, l+32); f32x2 acc pairs over (f, f+1), w natural pairs.
// Scalar leaky-relu production + 1-deep software pipeline.
// smem: refs[128][64] f32 | tars[128][72] f32 | ws[128][16] f32  = 76 KB
// ---------------------------------------------------------------------------
#define SMEM_A_BYTES (128*64*4 + 128*72*4 + 128*16*4)

__global__ __launch_bounds__(288, 2) void cvol_kernel(
    const float* __restrict__ ref, const float* __restrict__ tar,
    const float* __restrict__ pw)
{
    extern __shared__ char smem[];
    float* refs = (float*)smem;              // [128][64]
    float* tars = refs + 128*64;             // [128][72], cols -4..67 zero-padded
    float* ws   = tars + 128*72;             // [128][16]  (transposed pw)

    const int dv = blockIdx.x, h = blockIdx.y, b = blockIdx.z;
    const int tid = threadIdx.x;
    const int hr = h + dv - MDW;
    const bool rowok = (hr >= 0) && (hr < NH);

    // fill refs (vectorized float4)
    for (int i = tid; i < 128*16; i += 288) {
        int c = i >> 4, xq = i & 15;
        *(float4*)&refs[c*64 + 4*xq] =
            *(const float4*)&ref[((b*NC + c) << 12) + (h << 6) + 4*xq];
    }
    // fill tars (zero-padded borders)
    for (int i = tid; i < 128*72; i += 288) {
        int c = i / 72, k = i - c*72;
        int x = k - MDW;
        float v = 0.f;
        if (rowok && x >= 0 && x < NW) v = tar[((b*NC + c) << 12) + (hr << 6) + x];
        tars[i] = v;
    }
    // fill ws transposed: ws[c][f] = pw[f][c]
    for (int i = tid; i < 128*16; i += 288) {
        int c = i >> 4, f = i & 15;
        ws[i] = pw[f*NC + c];
    }
    __syncthreads();

    const int du   = tid >> 5;      // warp id = du (0..8)
    const int lane = tid & 31;

    const float* refp = refs + lane;              // pixel l      (stride 64/c)
    const float* tarp = tars + lane + du;         // pixel l+du-4 (stride 72/c)
    const ulonglong2* wp = (const ulonglong2*)ws; // [c][4] of ((f,f+1) pairs)

    u64 acc[16];                    // [fpair 0..7][pix 0..1]
#pragma unroll
    for (int i = 0; i < 16; i++) acc[i] = 0ull;

    // ---- software-pipelined mainloop (1-deep prefetch) ----
    float r0 = refp[0], r1 = refp[32];
    float t0 = tarp[0], t1 = tarp[32];
    ulonglong2 w0 = wp[0], w1 = wp[1], w2 = wp[2], w3 = wp[3];

#pragma unroll 4
    for (int c = 0; c < 128; c++) {
        // prefetch next iteration (clamped; c=127 reloads itself, unused)
        int cn = (c < 127) ? c + 1 : 127;
        float nr0 = refp[cn*64],      nr1 = refp[cn*64 + 32];
        float nt0 = tarp[cn*72],      nt1 = tarp[cn*72 + 32];
        ulonglong2 nw0 = wp[cn*4+0], nw1 = wp[cn*4+1];
        ulonglong2 nw2 = wp[cn*4+2], nw3 = wp[cn*4+3];

        // scalar production: q = lrelu(r*t, 0.1)
        float p0 = r0 * t0;
        float p1 = r1 * t1;
        float q0 = fmaxf(p0, 0.1f * p0);
        float q1 = fmaxf(p1, 0.1f * p1);
        u64 qa = pk2(q0, q0);
        u64 qb = pk2(q1, q1);

        acc[ 0] = ffma2(qa, w0.x, acc[ 0]);  acc[ 1] = ffma2(qb, w0.x, acc[ 1]);
        acc[ 2] = ffma2(qa, w0.y, acc[ 2]);  acc[ 3] = ffma2(qb, w0.y, acc[ 3]);
        acc[ 4] = ffma2(qa, w1.x, acc[ 4]);  acc[ 5] = ffma2(qb, w1.x, acc[ 5]);
        acc[ 6] = ffma2(qa, w1.y, acc[ 6]);  acc[ 7] = ffma2(qb, w1.y, acc[ 7]);
        acc[ 8] = ffma2(qa, w2.x, acc[ 8]);  acc[ 9] = ffma2(qb, w2.x, acc[ 9]);
        acc[10] = ffma2(qa, w2.y, acc[10]);  acc[11] = ffma2(qb, w2.y, acc[11]);
        acc[12] = ffma2(qa, w3.x, acc[12]);  acc[13] = ffma2(qb, w3.x, acc[13]);
        acc[14] = ffma2(qa, w3.y, acc[14]);  acc[15] = ffma2(qb, w3.y, acc[15]);

        r0 = nr0; r1 = nr1; t0 = nt0; t1 = nt1;
        w0 = nw0; w1 = nw1; w2 = nw2; w3 = nw3;
    }

    // epilogue: acc[2*fp+px] = ((f=2fp, f=2fp+1) at pixel (px ? lane+32 : lane))
    const int uv = du*9 + dv;
    const int pbase = (h << 6) + lane;
#pragma unroll
    for (int fp = 0; fp < 8; fp++) {
        float2 a0 = upk(acc[2*fp]);       // pixel lane
        float2 a1 = upk(acc[2*fp + 1]);   // pixel lane+32
        int f0 = 2*fp, f1 = 2*fp + 1;
        float* o0 = &g_cvol[(((b*NF + f0)*81 + uv) << 12) + pbase];
        float* o1 = &g_cvol[(((b*NF + f1)*81 + uv) << 12) + pbase];
        o0[0]  = a0.x;  o0[32] = a1.x;
        o1[0]  = a0.y;  o1[32] = a1.y;
    }
}

// ---------------------------------------------------------------------------
// Kernel B: flow_reg (argmax -> 7x7 mask -> masked softmax -> soft-argmax + entropies)
// one thread per (b*F, pixel); 131072 threads
// ---------------------------------------------------------------------------
__global__ __launch_bounds__(256) void flowreg_kernel(float* __restrict__ out)
{
    int g = blockIdx.x * 256 + threadIdx.x;     // 0..131071
    int bf = g >> 12, pix = g & 4095;
    const float* base = g_cvol + ((bf*81) << 12) + pix;

    float v[81];
#pragma unroll
    for (int i = 0; i < 81; i++) v[i] = base[i << 12];

    float m = v[0]; int am = 0;
#pragma unroll
    for (int i = 1; i < 81; i++) if (v[i] > m) { m = v[i]; am = i; }
    int ub = am / 9, vb = am - 9*(am/9);

    float S = 0.f, T = 0.f, Sx = 0.f, Sy = 0.f, gS = 0.f, gT = 0.f;
#pragma unroll
    for (int u = 0; u < 9; u++) {
#pragma unroll
        for (int w = 0; w < 9; w++) {
            float d = v[u*9 + w] - m;
            float e = __expf(d);
            gS += e; gT += e*d;
            bool inm = (abs(u - ub) <= 3) && (abs(w - vb) <= 3);
            if (inm) {
                S += e; T += e*d;
                Sx += e * (float)(u - 4);
                Sy += e * (float)(w - 4);
            }
        }
    }
    float inv  = 1.f / S;
    float ginv = 1.f / gS;
    float outx = Sx * inv;
    float outy = Sy * inv;
    float lent = (logf(S)  - T  * inv ) * 0.25694936f;   // 1/log(49)
    float gent = (logf(gS) - gT * ginv) * 0.22756237f;   // 1/log(81)

    out[(bf*4 + 0)*NHW + pix] = outx;
    out[(bf*4 + 1)*NHW + pix] = outy;
    out[(bf*4 + 2)*NHW + pix] = lent;
    out[(bf*4 + 3)*NHW + pix] = gent;
}

// ---------------------------------------------------------------------------
// Kernel C: bilinear backward warp of tar_feat by flow (hypothesis f=0)
// one thread per output element (b,c,y,x); 1048576 threads
// ---------------------------------------------------------------------------
__global__ __launch_bounds__(256) void warp_kernel(
    const float* __restrict__ tar, float* __restrict__ out)
{
    int g = blockIdx.x * 256 + threadIdx.x;       // 0..1048575
    int x = g & 63, y = (g >> 6) & 63, c = (g >> 12) & 127, b = g >> 19;

    const float* fbase = out + b*(NF*4*NHW) + (y << 6) + x;  // bf = b*16+0, ch 0/1
    float fx = fbase[0];
    float fy = fbase[NHW];

    float px = (float)x + fx;
    float py = (float)y + fy;
    bool inb = (fabsf(2.0f*px/63.0f - 1.0f) < 1.0f) &&
               (fabsf(2.0f*py/63.0f - 1.0f) < 1.0f);

    float x0f = floorf(px), y0f = floorf(py);
    float wx = px - x0f, wy = py - y0f;
    int x0 = (int)x0f, y0 = (int)y0f;

    const float* img = tar + ((b*NC + c) << 12);
    float s = 0.f;
#pragma unroll
    for (int dy = 0; dy < 2; dy++) {
#pragma unroll
        for (int dx = 0; dx < 2; dx++) {
            int xi = x0 + dx, yi = y0 + dy;
            bool ok = (xi >= 0) && (xi < NW) && (yi >= 0) && (yi < NH);
            float wgt = (dx ? wx : 1.f - wx) * (dy ? wy : 1.f - wy);
            int xc = min(max(xi, 0), NW-1), yc = min(max(yi, 0), NH-1);
            s += img[(yc << 6) + xc] * (ok ? wgt : 0.f);
        }
    }
    out[OUT1_ELEMS + g] = s * (inb ? 1.f : 0.f);
}

// ---------------------------------------------------------------------------
extern "C" void kernel_launch(void* const* d_in, const int* in_sizes, int n_in,
                              void* d_out, int out_size)
{
    const float* ref = (const float*)d_in[0];
    const float* tar = (const float*)d_in[1];
    const float* pw  = (const float*)d_in[2];
    float* out = (float*)d_out;

    cudaFuncSetAttribute(cvol_kernel,
                         cudaFuncAttributeMaxDynamicSharedMemorySize, SMEM_A_BYTES);

    dim3 gA(UDIM, NH, NB);
    cvol_kernel<<<gA, 288, SMEM_A_BYTES>>>(ref, tar, pw);
    flowreg_kernel<<<(NB*NF*NHW)/256, 256>>>(out);
    warp_kernel<<<WARP_ELEMS/256, 256>>>(tar, out);
}

// round 7
// speedup vs baseline: 1.0551x; 1.0551x over previous
#include <cuda_runtime.h>
#include <cstdint>

// Problem constants
#define MDW   4
#define UDIM  9          // 2*MD+1
#define NB    2
#define NC    128
#define NH    64
#define NW    64
#define NF    16
#define NHW   4096
#define OUT1_ELEMS (NB*NF*4*NHW)        // 524288
#define WARP_ELEMS (NB*NC*NHW)          // 1048576

// cvol scratch: [b*F][uv=du*9+dv][h][w]  (42.5 MB)
__device__ float g_cvol[NB*NF*81*NHW];

typedef unsigned long long u64;

__device__ __forceinline__ u64 pk2(float x, float y) {
    u64 r; asm("mov.b64 %0, {%1,%2};" : "=l"(r) : "f"(x), "f"(y)); return r;
}
__device__ __forceinline__ float2 upk(u64 v) {
    float2 f; asm("mov.b64 {%0,%1}, %2;" : "=f"(f.x), "=f"(f.y) : "l"(v)); return f;
}
__device__ __forceinline__ u64 ffma2(u64 a, u64 b, u64 c) {
    u64 d; asm("fma.rn.f32x2 %0, %1, %2, %3;" : "=l"(d) : "l"(a), "l"(b), "l"(c)); return d;
}

// ---------------------------------------------------------------------------
// Kernel A: cost volume + channel projection.
// grid (dv=9, h=64, b=2), block 288 (9 warps, warp <-> du), 3 blocks/SM.
// Channels staged in 64-ch chunks so smem fits 3 CTAs:
//   refs[64][64] f32 (16KB) | tars[64][72] f32 (18KB) | ws[128][16] f32 (8KB)
// lane <-> pixels (l, l+32); f32x2 acc pairs over (f, f+1), w natural pairs.
// ---------------------------------------------------------------------------
#define KC 64
#define SMEM_A_BYTES (KC*64*4 + KC*72*4 + 128*16*4)   // 43008

__global__ __launch_bounds__(288, 3) void cvol_kernel(
    const float* __restrict__ ref, const float* __restrict__ tar,
    const float* __restrict__ pw)
{
    extern __shared__ char smem[];
    float* refs = (float*)smem;              // [KC][64]
    float* tars = refs + KC*64;              // [KC][72], cols 0..3 & 68..71 always 0
    float* ws   = tars + KC*72;              // [128][16]  (transposed pw)

    const int dv = blockIdx.x, h = blockIdx.y, b = blockIdx.z;
    const int tid = threadIdx.x;
    const int hr = h + dv - MDW;
    const bool rowok = (hr >= 0) && (hr < NH);

    // ws transposed: ws[c][f] = pw[f][c]  (once)
    for (int i = tid; i < 128*16; i += 288) {
        int c = i >> 4, f = i & 15;
        ws[i] = pw[f*NC + c];
    }
    // zero tars border columns once (never touched again)
    for (int i = tid; i < KC*8; i += 288) {
        int c = i >> 3, k = i & 7;
        tars[c*72 + (k < 4 ? k : k + 64)] = 0.f;
    }

    const int du   = tid >> 5;      // warp id = du (0..8)
    const int lane = tid & 31;

    u64 acc[16];                    // [fpair 0..7][pix 0..1]
#pragma unroll
    for (int i = 0; i < 16; i++) acc[i] = 0ull;

    for (int k0 = 0; k0 < 128; k0 += KC) {
        __syncthreads();   // previous chunk fully consumed / setup done
        // refs chunk: KC rows x 16 float4
        for (int i = tid; i < KC*16; i += 288) {
            int c = i >> 4, xq = i & 15;
            *(float4*)&refs[c*64 + 4*xq] =
                *(const float4*)&ref[((b*NC + k0 + c) << 12) + (h << 6) + 4*xq];
        }
        // tars chunk interior (cols 4..67  <=>  x 0..63)
        if (rowok) {
            for (int i = tid; i < KC*16; i += 288) {
                int c = i >> 4, xq = i & 15;
                *(float4*)&tars[c*72 + 4 + 4*xq] =
                    *(const float4*)&tar[((b*NC + k0 + c) << 12) + (hr << 6) + 4*xq];
            }
        } else {
            float4 z = make_float4(0.f, 0.f, 0.f, 0.f);
            for (int i = tid; i < KC*16; i += 288) {
                int c = i >> 4, xq = i & 15;
                *(float4*)&tars[c*72 + 4 + 4*xq] = z;
            }
        }
        __syncthreads();

        const float* refp = refs + lane;               // pixel l      (stride 64/c)
        const float* tarp = tars + lane + du;          // pixel l+du-4 (stride 72/c)
        const ulonglong2* wp = (const ulonglong2*)(ws + k0*16);

#pragma unroll 8
        for (int c = 0; c < KC; c++) {
            float r0 = refp[c*64];
            float r1 = refp[c*64 + 32];
            float t0 = tarp[c*72];
            float t1 = tarp[c*72 + 32];
            float p0 = r0 * t0;
            float p1 = r1 * t1;
            float q0 = fmaxf(p0, 0.1f * p0);
            float q1 = fmaxf(p1, 0.1f * p1);
            u64 qa = pk2(q0, q0);
            u64 qb = pk2(q1, q1);
            ulonglong2 w0 = wp[c*4 + 0];
            ulonglong2 w1 = wp[c*4 + 1];
            ulonglong2 w2 = wp[c*4 + 2];
            ulonglong2 w3 = wp[c*4 + 3];
            acc[ 0] = ffma2(qa, w0.x, acc[ 0]);  acc[ 1] = ffma2(qb, w0.x, acc[ 1]);
            acc[ 2] = ffma2(qa, w0.y, acc[ 2]);  acc[ 3] = ffma2(qb, w0.y, acc[ 3]);
            acc[ 4] = ffma2(qa, w1.x, acc[ 4]);  acc[ 5] = ffma2(qb, w1.x, acc[ 5]);
            acc[ 6] = ffma2(qa, w1.y, acc[ 6]);  acc[ 7] = ffma2(qb, w1.y, acc[ 7]);
            acc[ 8] = ffma2(qa, w2.x, acc[ 8]);  acc[ 9] = ffma2(qb, w2.x, acc[ 9]);
            acc[10] = ffma2(qa, w2.y, acc[10]);  acc[11] = ffma2(qb, w2.y, acc[11]);
            acc[12] = ffma2(qa, w3.x, acc[12]);  acc[13] = ffma2(qb, w3.x, acc[13]);
            acc[14] = ffma2(qa, w3.y, acc[14]);  acc[15] = ffma2(qb, w3.y, acc[15]);
        }
    }

    // epilogue: acc[2*fp+px] = ((f=2fp, f=2fp+1) at pixel (px ? lane+32 : lane))
    const int uv = du*9 + dv;
    const int pbase = (h << 6) + lane;
#pragma unroll
    for (int fp = 0; fp < 8; fp++) {
        float2 a0 = upk(acc[2*fp]);       // pixel lane
        float2 a1 = upk(acc[2*fp + 1]);   // pixel lane+32
        int f0 = 2*fp, f1 = 2*fp + 1;
        float* o0 = &g_cvol[(((b*NF + f0)*81 + uv) << 12) + pbase];
        float* o1 = &g_cvol[(((b*NF + f1)*81 + uv) << 12) + pbase];
        o0[0]  = a0.x;  o0[32] = a1.x;
        o1[0]  = a0.y;  o1[32] = a1.y;
    }
}

// ---------------------------------------------------------------------------
// Kernel B: flow_reg (argmax -> 7x7 mask -> masked softmax -> soft-argmax + entropies)
// one thread per (b*F, pixel); 131072 threads
// ---------------------------------------------------------------------------
__global__ __launch_bounds__(256) void flowreg_kernel(float* __restrict__ out)
{
    int g = blockIdx.x * 256 + threadIdx.x;     // 0..131071
    int bf = g >> 12, pix = g & 4095;
    const float* base = g_cvol + ((bf*81) << 12) + pix;

    float v[81];
#pragma unroll
    for (int i = 0; i < 81; i++) v[i] = base[i << 12];

    float m = v[0]; int am = 0;
#pragma unroll
    for (int i = 1; i < 81; i++) if (v[i] > m) { m = v[i]; am = i; }
    int ub = am / 9, vb = am - 9*(am/9);

    float S = 0.f, T = 0.f, Sx = 0.f, Sy = 0.f, gS = 0.f, gT = 0.f;
#pragma unroll
    for (int u = 0; u < 9; u++) {
#pragma unroll
        for (int w = 0; w < 9; w++) {
            float d = v[u*9 + w] - m;
            float e = __expf(d);
            gS += e; gT += e*d;
            bool inm = (abs(u - ub) <= 3) && (abs(w - vb) <= 3);
            if (inm) {
                S += e; T += e*d;
                Sx += e * (float)(u - 4);
                Sy += e * (float)(w - 4);
            }
        }
    }
    float inv  = 1.f / S;
    float ginv = 1.f / gS;
    float outx = Sx * inv;
    float outy = Sy * inv;
    float lent = (logf(S)  - T  * inv ) * 0.25694936f;   // 1/log(49)
    float gent = (logf(gS) - gT * ginv) * 0.22756237f;   // 1/log(81)

    out[(bf*4 + 0)*NHW + pix] = outx;
    out[(bf*4 + 1)*NHW + pix] = outy;
    out[(bf*4 + 2)*NHW + pix] = lent;
    out[(bf*4 + 3)*NHW + pix] = gent;
}

// ---------------------------------------------------------------------------
// Kernel C: bilinear backward warp of tar_feat by flow (hypothesis f=0)
// one thread per output element (b,c,y,x); 1048576 threads
// ---------------------------------------------------------------------------
__global__ __launch_bounds__(256) void warp_kernel(
    const float* __restrict__ tar, float* __restrict__ out)
{
    int g = blockIdx.x * 256 + threadIdx.x;       // 0..1048575
    int x = g & 63, y = (g >> 6) & 63, c = (g >> 12) & 127, b = g >> 19;

    const float* fbase = out + b*(NF*4*NHW) + (y << 6) + x;  // bf = b*16+0, ch 0/1
    float fx = fbase[0];
    float fy = fbase[NHW];

    float px = (float)x + fx;
    float py = (float)y + fy;
    bool inb = (fabsf(2.0f*px/63.0f - 1.0f) < 1.0f) &&
               (fabsf(2.0f*py/63.0f - 1.0f) < 1.0f);

    float x0f = floorf(px), y0f = floorf(py);
    float wx = px - x0f, wy = py - y0f;
    int x0 = (int)x0f, y0 = (int)y0f;

    const float* img = tar + ((b*NC + c) << 12);
    float s = 0.f;
#pragma unroll
    for (int dy = 0; dy < 2; dy++) {
#pragma unroll
        for (int dx = 0; dx < 2; dx++) {
            int xi = x0 + dx, yi = y0 + dy;
            bool ok = (xi >= 0) && (xi < NW) && (yi >= 0) && (yi < NH);
            float wgt = (dx ? wx : 1.f - wx) * (dy ? wy : 1.f - wy);
            int xc = min(max(xi, 0), NW-1), yc = min(max(yi, 0), NH-1);
            s += img[(yc << 6) + xc] * (ok ? wgt : 0.f);
        }
    }
    out[OUT1_ELEMS + g] = s * (inb ? 1.f : 0.f);
}

// ---------------------------------------------------------------------------
extern "C" void kernel_launch(void* const* d_in, const int* in_sizes, int n_in,
                              void* d_out, int out_size)
{
    const float* ref = (const float*)d_in[0];
    const float* tar = (const float*)d_in[1];
    const float* pw  = (const float*)d_in[2];
    float* out = (float*)d_out;

    cudaFuncSetAttribute(cvol_kernel,
                         cudaFuncAttributeMaxDynamicSharedMemorySize, SMEM_A_BYTES);

    dim3 gA(UDIM, NH, NB);
    cvol_kernel<<<gA, 288, SMEM_A_BYTES>>>(ref, tar, pw);
    flowreg_kernel<<<(NB*NF*NHW)/256, 256>>>(out);
    warp_kernel<<<WARP_ELEMS/256, 256>>>(tar, out);
}

// round 8
// speedup vs baseline: 1.1475x; 1.0876x over previous
#include <cuda_runtime.h>
#include <cstdint>

// Problem constants
#define MDW   4
#define UDIM  9          // 2*MD+1
#define NB    2
#define NC    128
#define NH    64
#define NW    64
#define NF    16
#define NHW   4096
#define OUT1_ELEMS (NB*NF*4*NHW)        // 524288
#define WARP_ELEMS (NB*NC*NHW)          // 1048576

// cvol scratch: [b*F][uv=du*9+dv][h][w]  (42.5 MB)
__device__ float g_cvol[NB*NF*81*NHW];

typedef unsigned long long u64;

__device__ __forceinline__ u64 pk2(float x, float y) {
    u64 r; asm("mov.b64 %0, {%1,%2};" : "=l"(r) : "f"(x), "f"(y)); return r;
}
__device__ __forceinline__ float2 upk(u64 v) {
    float2 f; asm("mov.b64 {%0,%1}, %2;" : "=f"(f.x), "=f"(f.y) : "l"(v)); return f;
}
__device__ __forceinline__ u64 ffma2(u64 a, u64 b, u64 c) {
    u64 d; asm("fma.rn.f32x2 %0, %1, %2, %3;" : "=l"(d) : "l"(a), "l"(b), "l"(c)); return d;
}

// ---------------------------------------------------------------------------
// Kernel A: cost volume + channel projection.
// grid (dv=9, h2=32, b=2), block 288 (9 warps, warp <-> du), 2 blocks/SM.
// Each block covers TWO image rows (h0, h0+1); smem stores the two rows
// INTERLEAVED [c][x][r] so one LDS.64 feeds both rows -> LDS per MAC halved.
// Lane covers 4 pixels: (x=l, x=l+32) x (row0,row1), all 16 f.
// Channels staged in 64-ch chunks:
//   refs[64][64][2] (32KB) | tars[64][72][2] (36.9KB) | ws[128][16] (8KB)
// ---------------------------------------------------------------------------
#define KC 64
#define SMEM_A_BYTES (KC*64*2*4 + KC*72*2*4 + 128*16*4)   // 78848

__global__ __launch_bounds__(288, 2) void cvol_kernel(
    const float* __restrict__ ref, const float* __restrict__ tar,
    const float* __restrict__ pw)
{
    extern __shared__ char smem[];
    float* refs = (float*)smem;              // [KC][64][2]
    float* tars = refs + KC*128;             // [KC][72][2], xp 0..3 & 68..71 zero
    float* ws   = tars + KC*144;             // [128][16]  (transposed pw)

    const int dv = blockIdx.x, b = blockIdx.z;
    const int h0 = blockIdx.y * 2;
    const int tid = threadIdx.x;
    const int hr0 = h0 + dv - MDW;
    const int hr1 = hr0 + 1;
    const bool ok0 = (hr0 >= 0) && (hr0 < NH);
    const bool ok1 = (hr1 >= 0) && (hr1 < NH);

    // ws transposed: ws[c][f] = pw[f][c]  (once)
    for (int i = tid; i < 128*16; i += 288) {
        int c = i >> 4, f = i & 15;
        ws[i] = pw[f*NC + c];
    }
    // zero tars border columns once (interior writes never touch them)
    for (int i = tid; i < KC*16; i += 288) {
        int c = i >> 4, k = i & 15;
        tars[c*144 + (k < 8 ? k : k + 128)] = 0.f;
    }

    const int du   = tid >> 5;      // warp id = du (0..8)
    const int lane = tid & 31;

    u64 acc[32];                    // [px 0..3][fpair 0..7]
#pragma unroll
    for (int i = 0; i < 32; i++) acc[i] = 0ull;

    for (int k0 = 0; k0 < 128; k0 += KC) {
        __syncthreads();   // previous chunk fully consumed / border zeros done
        // refs chunk: interleave rows h0, h0+1
        for (int i = tid; i < KC*16; i += 288) {
            int c = i >> 4, xq = i & 15;
            const float* g0 = &ref[((b*NC + k0 + c) << 12) + (h0 << 6) + 4*xq];
            float4 a = *(const float4*)g0;
            float4 bb = *(const float4*)(g0 + 64);
            float* d = &refs[c*128 + 8*xq];
            *(float2*)(d + 0) = make_float2(a.x, bb.x);
            *(float2*)(d + 2) = make_float2(a.y, bb.y);
            *(float2*)(d + 4) = make_float2(a.z, bb.z);
            *(float2*)(d + 6) = make_float2(a.w, bb.w);
        }
        // tars chunk interior (xp 4..67), rows hr0, hr1 interleaved
        for (int i = tid; i < KC*16; i += 288) {
            int c = i >> 4, xq = i & 15;
            const float* gb = &tar[((b*NC + k0 + c) << 12) + 4*xq];
            float4 z = make_float4(0.f, 0.f, 0.f, 0.f);
            float4 a = ok0 ? *(const float4*)(gb + (hr0 << 6)) : z;
            float4 bb = ok1 ? *(const float4*)(gb + (hr1 << 6)) : z;
            float* d = &tars[c*144 + 8 + 8*xq];
            *(float2*)(d + 0) = make_float2(a.x, bb.x);
            *(float2*)(d + 2) = make_float2(a.y, bb.y);
            *(float2*)(d + 4) = make_float2(a.z, bb.z);
            *(float2*)(d + 6) = make_float2(a.w, bb.w);
        }
        __syncthreads();

        const float* refp = refs + 2*lane;             // (rows r0,r1) at x=lane
        const float* tarp = tars + 2*(lane + du);      // (rows r0,r1) at x=lane+du-4
        const ulonglong2* wp = (const ulonglong2*)(ws + k0*16);

#pragma unroll 8
        for (int c = 0; c < KC; c++) {
            float2 r0 = *(const float2*)&refp[c*128];        // x=l    rows (0,1)
            float2 r1 = *(const float2*)&refp[c*128 + 64];   // x=l+32
            float2 t0 = *(const float2*)&tarp[c*144];
            float2 t1 = *(const float2*)&tarp[c*144 + 64];
            float p00 = r0.x * t0.x;   // (x=l,    row0)
            float p01 = r0.y * t0.y;   // (x=l,    row1)
            float p10 = r1.x * t1.x;   // (x=l+32, row0)
            float p11 = r1.y * t1.y;   // (x=l+32, row1)
            u64 q0 = pk2(fmaxf(p00, 0.1f*p00), fmaxf(p00, 0.1f*p00));
            u64 q1 = pk2(fmaxf(p01, 0.1f*p01), fmaxf(p01, 0.1f*p01));
            u64 q2 = pk2(fmaxf(p10, 0.1f*p10), fmaxf(p10, 0.1f*p10));
            u64 q3 = pk2(fmaxf(p11, 0.1f*p11), fmaxf(p11, 0.1f*p11));
            ulonglong2 w0 = wp[c*4 + 0];
            ulonglong2 w1 = wp[c*4 + 1];
            ulonglong2 w2 = wp[c*4 + 2];
            ulonglong2 w3 = wp[c*4 + 3];
            acc[ 0] = ffma2(q0, w0.x, acc[ 0]);  acc[ 8] = ffma2(q1, w0.x, acc[ 8]);
            acc[16] = ffma2(q2, w0.x, acc[16]);  acc[24] = ffma2(q3, w0.x, acc[24]);
            acc[ 1] = ffma2(q0, w0.y, acc[ 1]);  acc[ 9] = ffma2(q1, w0.y, acc[ 9]);
            acc[17] = ffma2(q2, w0.y, acc[17]);  acc[25] = ffma2(q3, w0.y, acc[25]);
            acc[ 2] = ffma2(q0, w1.x, acc[ 2]);  acc[10] = ffma2(q1, w1.x, acc[10]);
            acc[18] = ffma2(q2, w1.x, acc[18]);  acc[26] = ffma2(q3, w1.x, acc[26]);
            acc[ 3] = ffma2(q0, w1.y, acc[ 3]);  acc[11] = ffma2(q1, w1.y, acc[11]);
            acc[19] = ffma2(q2, w1.y, acc[19]);  acc[27] = ffma2(q3, w1.y, acc[27]);
            acc[ 4] = ffma2(q0, w2.x, acc[ 4]);  acc[12] = ffma2(q1, w2.x, acc[12]);
            acc[20] = ffma2(q2, w2.x, acc[20]);  acc[28] = ffma2(q3, w2.x, acc[28]);
            acc[ 5] = ffma2(q0, w2.y, acc[ 5]);  acc[13] = ffma2(q1, w2.y, acc[13]);
            acc[21] = ffma2(q2, w2.y, acc[21]);  acc[29] = ffma2(q3, w2.y, acc[29]);
            acc[ 6] = ffma2(q0, w3.x, acc[ 6]);  acc[14] = ffma2(q1, w3.x, acc[14]);
            acc[22] = ffma2(q2, w3.x, acc[22]);  acc[30] = ffma2(q3, w3.x, acc[30]);
            acc[ 7] = ffma2(q0, w3.y, acc[ 7]);  acc[15] = ffma2(q1, w3.y, acc[15]);
            acc[23] = ffma2(q2, w3.y, acc[23]);  acc[31] = ffma2(q3, w3.y, acc[31]);
        }
    }

    // epilogue
    const int uv = du*9 + dv;
    const int p00 = (h0 << 6) + lane;        // (row0, x=l)
    const int p10 = p00 + 64;                // (row1, x=l)
#pragma unroll
    for (int fp = 0; fp < 8; fp++) {
        float2 v0 = upk(acc[fp]);        // (f0,f1) @ (row0, l)
        float2 v1 = upk(acc[8 + fp]);    // @ (row1, l)
        float2 v2 = upk(acc[16 + fp]);   // @ (row0, l+32)
        float2 v3 = upk(acc[24 + fp]);   // @ (row1, l+32)
        int f0 = 2*fp, f1 = 2*fp + 1;
        float* o0 = &g_cvol[((b*NF + f0)*81 + uv) << 12];
        float* o1 = &g_cvol[((b*NF + f1)*81 + uv) << 12];
        o0[p00] = v0.x;  o0[p10] = v1.x;  o0[p00 + 32] = v2.x;  o0[p10 + 32] = v3.x;
        o1[p00] = v0.y;  o1[p10] = v1.y;  o1[p00 + 32] = v2.y;  o1[p10 + 32] = v3.y;
    }
}

// ---------------------------------------------------------------------------
// Kernel B: flow_reg (argmax -> 7x7 mask -> masked softmax -> soft-argmax + entropies)
// one thread per (b*F, pixel); 131072 threads
// ---------------------------------------------------------------------------
__global__ __launch_bounds__(256) void flowreg_kernel(float* __restrict__ out)
{
    int g = blockIdx.x * 256 + threadIdx.x;     // 0..131071
    int bf = g >> 12, pix = g & 4095;
    const float* base = g_cvol + ((bf*81) << 12) + pix;

    float v[81];
#pragma unroll
    for (int i = 0; i < 81; i++) v[i] = base[i << 12];

    float m = v[0]; int am = 0;
#pragma unroll
    for (int i = 1; i < 81; i++) if (v[i] > m) { m = v[i]; am = i; }
    int ub = am / 9, vb = am - 9*(am/9);

    float S = 0.f, T = 0.f, Sx = 0.f, Sy = 0.f, gS = 0.f, gT = 0.f;
#pragma unroll
    for (int u = 0; u < 9; u++) {
#pragma unroll
        for (int w = 0; w < 9; w++) {
            float d = v[u*9 + w] - m;
            float e = __expf(d);
            gS += e; gT += e*d;
            bool inm = (abs(u - ub) <= 3) && (abs(w - vb) <= 3);
            if (inm) {
                S += e; T += e*d;
                Sx += e * (float)(u - 4);
                Sy += e * (float)(w - 4);
            }
        }
    }
    float inv  = 1.f / S;
    float ginv = 1.f / gS;
    float outx = Sx * inv;
    float outy = Sy * inv;
    float lent = (logf(S)  - T  * inv ) * 0.25694936f;   // 1/log(49)
    float gent = (logf(gS) - gT * ginv) * 0.22756237f;   // 1/log(81)

    out[(bf*4 + 0)*NHW + pix] = outx;
    out[(bf*4 + 1)*NHW + pix] = outy;
    out[(bf*4 + 2)*NHW + pix] = lent;
    out[(bf*4 + 3)*NHW + pix] = gent;
}

// ---------------------------------------------------------------------------
// Kernel C: bilinear backward warp of tar_feat by flow (hypothesis f=0)
// one thread per output element (b,c,y,x); 1048576 threads
// ---------------------------------------------------------------------------
__global__ __launch_bounds__(256) void warp_kernel(
    const float* __restrict__ tar, float* __restrict__ out)
{
    int g = blockIdx.x * 256 + threadIdx.x;       // 0..1048575
    int x = g & 63, y = (g >> 6) & 63, c = (g >> 12) & 127, b = g >> 19;

    const float* fbase = out + b*(NF*4*NHW) + (y << 6) + x;  // bf = b*16+0, ch 0/1
    float fx = fbase[0];
    float fy = fbase[NHW];

    float px = (float)x + fx;
    float py = (float)y + fy;
    bool inb = (fabsf(2.0f*px/63.0f - 1.0f) < 1.0f) &&
               (fabsf(2.0f*py/63.0f - 1.0f) < 1.0f);

    float x0f = floorf(px), y0f = floorf(py);
    float wx = px - x0f, wy = py - y0f;
    int x0 = (int)x0f, y0 = (int)y0f;

    const float* img = tar + ((b*NC + c) << 12);
    float s = 0.f;
#pragma unroll
    for (int dy = 0; dy < 2; dy++) {
#pragma unroll
        for (int dx = 0; dx < 2; dx++) {
            int xi = x0 + dx, yi = y0 + dy;
            bool ok = (xi >= 0) && (xi < NW) && (yi >= 0) && (yi < NH);
            float wgt = (dx ? wx : 1.f - wx) * (dy ? wy : 1.f - wy);
            int xc = min(max(xi, 0), NW-1), yc = min(max(yi, 0), NH-1);
            s += img[(yc << 6) + xc] * (ok ? wgt : 0.f);
        }
    }
    out[OUT1_ELEMS + g] = s * (inb ? 1.f : 0.f);
}

// ---------------------------------------------------------------------------
extern "C" void kernel_launch(void* const* d_in, const int* in_sizes, int n_in,
                              void* d_out, int out_size)
{
    const float* ref = (const float*)d_in[0];
    const float* tar = (const float*)d_in[1];
    const float* pw  = (const float*)d_in[2];
    float* out = (float*)d_out;

    cudaFuncSetAttribute(cvol_kernel,
                         cudaFuncAttributeMaxDynamicSharedMemorySize, SMEM_A_BYTES);

    dim3 gA(UDIM, NH/2, NB);
    cvol_kernel<<<gA, 288, SMEM_A_BYTES>>>(ref, tar, pw);
    flowreg_kernel<<<(NB*NF*NHW)/256, 256>>>(out);
    warp_kernel<<<WARP_ELEMS/256, 256>>>(tar, out);
}